// round 4
// baseline (speedup 1.0000x reference)
#include <cuda_runtime.h>
#include <stdint.h>

// ---------------------------------------------------------------------------
// GNN_Layer_Init: out[N,32] = segment_sum_e( edge_val[e] * weight[edge_col[e],:],
//                                            seg=edge_row[e] ) + bias
// N = 100000, D = 32, E = 1.6M
//
// Inputs (metadata order):
//   d_in[0] edge_row  int32 [E]   (JAX silently downcasts int64->int32 w/o x64)
//   d_in[1] edge_col  int32 [E]
//   d_in[2] edge_val  fp32  [E]
//   d_in[3] weight    fp32  [N,32]
//   d_in[4] bias      fp32  [32]
// Output: fp32 [N,32]
//
// Strategy: init out with bias, then one thread per edge doing
// 8 x (LDG.128 weight chunk; red.global.add.v4.f32 into out row).
// weight (12.8MB) and out (12.8MB) are L2-resident -> atomics hit L2.
// ---------------------------------------------------------------------------

#define D 32
#define DV 8  // D/4 float4 chunks per row

__global__ void init_out_kernel(float4* __restrict__ out,
                                const float* __restrict__ bias,
                                int n_vec)  // n_vec = N * DV
{
    int t = blockIdx.x * blockDim.x + threadIdx.x;
    if (t >= n_vec) return;
    const float4* b4 = reinterpret_cast<const float4*>(bias);
    out[t] = b4[t & (DV - 1)];
}

__device__ __forceinline__ void red_add_v4(float* addr, float4 v)
{
    asm volatile("red.global.add.v4.f32 [%0], {%1, %2, %3, %4};"
                 :: "l"(addr), "f"(v.x), "f"(v.y), "f"(v.z), "f"(v.w)
                 : "memory");
}

__global__ void spmm_edge_kernel(const int* __restrict__ edge_row,
                                 const int* __restrict__ edge_col,
                                 const float* __restrict__ edge_val,
                                 const float* __restrict__ weight,
                                 float* __restrict__ out,
                                 int E)
{
    int e = blockIdx.x * blockDim.x + threadIdx.x;
    if (e >= E) return;

    int r = edge_row[e];
    int c = edge_col[e];
    float v = edge_val[e];

    const float4* w4 = reinterpret_cast<const float4*>(weight + (size_t)c * D);
    float* orow = out + (size_t)r * D;

    // 8 independent 16B loads -> 8 independent 16B reductions. MLP ~8 per
    // thread hides L2 hit latency; red.v4 quarters the atomic-issue count
    // vs scalar atomicAdd.
#pragma unroll
    for (int j = 0; j < DV; j++) {
        float4 w = __ldg(&w4[j]);
        float4 p;
        p.x = v * w.x; p.y = v * w.y; p.z = v * w.z; p.w = v * w.w;
        red_add_v4(orow + j * 4, p);
    }
}

extern "C" void kernel_launch(void* const* d_in, const int* in_sizes, int n_in,
                              void* d_out, int out_size)
{
    const int*   edge_row = (const int*)d_in[0];
    const int*   edge_col = (const int*)d_in[1];
    const float* edge_val = (const float*)d_in[2];
    const float* weight   = (const float*)d_in[3];
    const float* bias     = (const float*)d_in[4];
    float*       out      = (float*)d_out;

    int E = in_sizes[0];
    int n_vec = out_size / 4;  // number of float4 elements in out

    {
        int threads = 256;
        int blocks = (n_vec + threads - 1) / threads;
        init_out_kernel<<<blocks, threads>>>((float4*)out, bias, n_vec);
    }
    {
        int threads = 256;
        int blocks = (E + threads - 1) / threads;
        spmm_edge_kernel<<<blocks, threads>>>(edge_row, edge_col, edge_val,
                                              weight, out, E);
    }
}

// round 5
// speedup vs baseline: 2.4115x; 2.4115x over previous
#include <cuda_runtime.h>
#include <stdint.h>

// ---------------------------------------------------------------------------
// GNN_Layer_Init: out[N,32] = segment_sum_e( edge_val[e] * weight[edge_col[e],:],
//                                            seg=edge_row[e] ) + bias
// N = 100000, D = 32, E = 1.6M
//
// Inputs (metadata order):
//   d_in[0] edge_row  int32 [E]
//   d_in[1] edge_col  int32 [E]
//   d_in[2] edge_val  fp32  [E]
//   d_in[3] weight    fp32  [N,32]
//   d_in[4] bias      fp32  [32]
// Output: fp32 [N,32]
//
// R5: cooperative gather/scatter — 8 lanes per edge, one float4 per lane.
// A warp covers 4 edges; each LDG.128 / RED.v4 warp instruction touches only
// 4 distinct 128B lines (vs 32 with one-thread-per-edge), cutting L1TEX
// wavefronts 8x. ncu R4 showed L1=82.7% as the binding pipe.
// ---------------------------------------------------------------------------

#define D 32
#define DV 8  // float4 chunks per row

__global__ void init_out_kernel(float4* __restrict__ out,
                                const float* __restrict__ bias,
                                int n_vec)  // n_vec = N * DV
{
    int t = blockIdx.x * blockDim.x + threadIdx.x;
    if (t >= n_vec) return;
    const float4* b4 = reinterpret_cast<const float4*>(bias);
    out[t] = b4[t & (DV - 1)];
}

__device__ __forceinline__ void red_add_v4(float* addr, float4 v)
{
    asm volatile("red.global.add.v4.f32 [%0], {%1, %2, %3, %4};"
                 :: "l"(addr), "f"(v.x), "f"(v.y), "f"(v.z), "f"(v.w)
                 : "memory");
}

__global__ void spmm_edge_coop_kernel(const int* __restrict__ edge_row,
                                      const int* __restrict__ edge_col,
                                      const float* __restrict__ edge_val,
                                      const float* __restrict__ weight,
                                      float* __restrict__ out,
                                      int E)
{
    int tid = blockIdx.x * blockDim.x + threadIdx.x;
    int e = tid >> 3;        // edge index (8 lanes per edge)
    int j = tid & 7;         // float4 chunk within the row
    if (e >= E) return;

    // 8 lanes read the same edge scalars -> broadcast within the L1 wavefront.
    int   r = edge_row[e];
    int   c = edge_col[e];
    float v = edge_val[e];

    const float4* w4 = reinterpret_cast<const float4*>(weight) + (size_t)c * DV + j;
    float4 w = __ldg(w4);

    float4 p;
    p.x = v * w.x; p.y = v * w.y; p.z = v * w.z; p.w = v * w.w;

    red_add_v4(out + (size_t)r * D + j * 4, p);
}

extern "C" void kernel_launch(void* const* d_in, const int* in_sizes, int n_in,
                              void* d_out, int out_size)
{
    const int*   edge_row = (const int*)d_in[0];
    const int*   edge_col = (const int*)d_in[1];
    const float* edge_val = (const float*)d_in[2];
    const float* weight   = (const float*)d_in[3];
    const float* bias     = (const float*)d_in[4];
    float*       out      = (float*)d_out;

    int E = in_sizes[0];
    int n_vec = out_size / 4;  // number of float4 elements in out

    {
        int threads = 256;
        int blocks = (n_vec + threads - 1) / threads;
        init_out_kernel<<<blocks, threads>>>((float4*)out, bias, n_vec);
    }
    {
        int threads = 256;
        long long total = (long long)E * 8;
        int blocks = (int)((total + threads - 1) / threads);
        spmm_edge_coop_kernel<<<blocks, threads>>>(edge_row, edge_col, edge_val,
                                                   weight, out, E);
    }
}

// round 6
// speedup vs baseline: 2.5817x; 1.0706x over previous
#include <cuda_runtime.h>
#include <stdint.h>

// ---------------------------------------------------------------------------
// GNN_Layer_Init: out[N,32] = segment_sum_e( edge_val[e] * weight[edge_col[e],:],
//                                            seg=edge_row[e] ) + bias
// N = 100000, D = 32, E = 1.6M
//
// Inputs (metadata order):
//   d_in[0] edge_row  int32 [E]
//   d_in[1] edge_col  int32 [E]
//   d_in[2] edge_val  fp32  [E]
//   d_in[3] weight    fp32  [N,32]
//   d_in[4] bias      fp32  [32]
// Output: fp32 [N,32]
//
// R6: 8 lanes per edge-group, 4 edges per thread.
//  - Edge scalars loaded as int4/float4 (1 broadcast wavefront per group per
//    array instead of 4) -> scalar L1 wavefronts cut 4x.
//  - 4 independent gather->RED chains per thread (ILP=4).
// Gather LDG.128 and RED.v4 remain 1 L1 wavefront per edge each (floor
// without a global sort).
// ---------------------------------------------------------------------------

#define D 32
#define DV 8  // float4 chunks per row

__global__ void init_out_kernel(float4* __restrict__ out,
                                const float* __restrict__ bias,
                                int n_vec)  // n_vec = N * DV
{
    int t = blockIdx.x * blockDim.x + threadIdx.x;
    if (t >= n_vec) return;
    const float4* b4 = reinterpret_cast<const float4*>(bias);
    out[t] = b4[t & (DV - 1)];
}

__device__ __forceinline__ void red_add_v4(float* addr, float4 v)
{
    asm volatile("red.global.add.v4.f32 [%0], {%1, %2, %3, %4};"
                 :: "l"(addr), "f"(v.x), "f"(v.y), "f"(v.z), "f"(v.w)
                 : "memory");
}

__global__ __launch_bounds__(256)
void spmm_edge_coop4_kernel(const int4* __restrict__ edge_row4,
                            const int4* __restrict__ edge_col4,
                            const float4* __restrict__ edge_val4,
                            const float* __restrict__ weight,
                            float* __restrict__ out,
                            int n_groups)   // E / 4
{
    int tid = blockIdx.x * blockDim.x + threadIdx.x;
    int g = tid >> 3;        // edge-group index (4 edges)
    int j = tid & 7;         // float4 chunk within the 32-float row
    if (g >= n_groups) return;

    // All 8 lanes of the group read the same 16B -> single broadcast
    // wavefront per array; consecutive groups share 128B lines.
    int4   r4 = edge_row4[g];
    int4   c4 = edge_col4[g];
    float4 v4 = edge_val4[g];

    const float4* w4 = reinterpret_cast<const float4*>(weight);

    int   rr[4] = {r4.x, r4.y, r4.z, r4.w};
    int   cc[4] = {c4.x, c4.y, c4.z, c4.w};
    float vv[4] = {v4.x, v4.y, v4.z, v4.w};

    // 4 independent gather->scale->reduce chains (ILP = 4).
    float4 w[4];
#pragma unroll
    for (int k = 0; k < 4; k++)
        w[k] = __ldg(w4 + (size_t)cc[k] * DV + j);

#pragma unroll
    for (int k = 0; k < 4; k++) {
        float4 p;
        p.x = vv[k] * w[k].x;
        p.y = vv[k] * w[k].y;
        p.z = vv[k] * w[k].z;
        p.w = vv[k] * w[k].w;
        red_add_v4(out + (size_t)rr[k] * D + j * 4, p);
    }
}

extern "C" void kernel_launch(void* const* d_in, const int* in_sizes, int n_in,
                              void* d_out, int out_size)
{
    const int*   edge_row = (const int*)d_in[0];
    const int*   edge_col = (const int*)d_in[1];
    const float* edge_val = (const float*)d_in[2];
    const float* weight   = (const float*)d_in[3];
    const float* bias     = (const float*)d_in[4];
    float*       out      = (float*)d_out;

    int E = in_sizes[0];
    int n_vec = out_size / 4;  // number of float4 elements in out

    {
        int threads = 256;
        int blocks = (n_vec + threads - 1) / threads;
        init_out_kernel<<<blocks, threads>>>((float4*)out, bias, n_vec);
    }
    {
        // E = 1.6M is divisible by 4; guard anyway via group count.
        int n_groups = E >> 2;
        int threads = 256;
        long long total = (long long)n_groups * 8;
        int blocks = (int)((total + threads - 1) / threads);
        spmm_edge_coop4_kernel<<<blocks, threads>>>(
            (const int4*)edge_row, (const int4*)edge_col,
            (const float4*)edge_val, weight, out, n_groups);
    }
}

// round 9
// speedup vs baseline: 2.5957x; 1.0054x over previous
#include <cuda_runtime.h>
#include <stdint.h>

// ---------------------------------------------------------------------------
// GNN_Layer_Init: out[N,32] = segment_sum_e( edge_val[e] * weight[edge_col[e],:],
//                                            seg=edge_row[e] ) + bias
// N = 100000, D = 32, E = 1.6M
//
// Inputs (metadata order):
//   d_in[0] edge_row  int32 [E]
//   d_in[1] edge_col  int32 [E]
//   d_in[2] edge_val  fp32  [E]
//   d_in[3] weight    fp32  [N,32]
//   d_in[4] bias      fp32  [32]
// Output: fp32 [N,32]
//
// R7: same structure as R6 (8 lanes/edge, 4 edges/thread), but all loads
// bypass L1 allocation:
//   - weight gather: ld.global.cg  (L2-only; random rows -> ~10% L1 reuse,
//     allocation was pure fill-wavefront overhead at L1=78.5%)
//   - edge scalars:  ld.global.cs  (streaming, read exactly once)
//   - scatter: red.global.add.v4 (already L1-bypassing)
// ---------------------------------------------------------------------------

#define D 32
#define DV 8  // float4 chunks per row

__global__ void init_out_kernel(float4* __restrict__ out,
                                const float* __restrict__ bias,
                                int n_vec)  // n_vec = N * DV
{
    int t = blockIdx.x * blockDim.x + threadIdx.x;
    if (t >= n_vec) return;
    const float4* b4 = reinterpret_cast<const float4*>(bias);
    out[t] = b4[t & (DV - 1)];
}

__device__ __forceinline__ void red_add_v4(float* addr, float4 v)
{
    asm volatile("red.global.add.v4.f32 [%0], {%1, %2, %3, %4};"
                 :: "l"(addr), "f"(v.x), "f"(v.y), "f"(v.z), "f"(v.w)
                 : "memory");
}

__device__ __forceinline__ float4 ldg_cg_v4(const float4* p)
{
    float4 r;
    asm volatile("ld.global.cg.v4.f32 {%0, %1, %2, %3}, [%4];"
                 : "=f"(r.x), "=f"(r.y), "=f"(r.z), "=f"(r.w) : "l"(p));
    return r;
}

__device__ __forceinline__ int4 ldg_cs_i4(const int4* p)
{
    int4 r;
    asm volatile("ld.global.cs.v4.b32 {%0, %1, %2, %3}, [%4];"
                 : "=r"(r.x), "=r"(r.y), "=r"(r.z), "=r"(r.w) : "l"(p));
    return r;
}

__device__ __forceinline__ float4 ldg_cs_f4(const float4* p)
{
    float4 r;
    asm volatile("ld.global.cs.v4.f32 {%0, %1, %2, %3}, [%4];"
                 : "=f"(r.x), "=f"(r.y), "=f"(r.z), "=f"(r.w) : "l"(p));
    return r;
}

__global__ __launch_bounds__(256)
void spmm_edge_coop4_kernel(const int4* __restrict__ edge_row4,
                            const int4* __restrict__ edge_col4,
                            const float4* __restrict__ edge_val4,
                            const float* __restrict__ weight,
                            float* __restrict__ out,
                            int n_groups)   // E / 4
{
    int tid = blockIdx.x * blockDim.x + threadIdx.x;
    int g = tid >> 3;        // edge-group index (4 edges)
    int j = tid & 7;         // float4 chunk within the 32-float row
    if (g >= n_groups) return;

    // 8 lanes read the same 16B -> single broadcast wavefront per array.
    int4   r4 = ldg_cs_i4(edge_row4 + g);
    int4   c4 = ldg_cs_i4(edge_col4 + g);
    float4 v4 = ldg_cs_f4(edge_val4 + g);

    const float4* w4 = reinterpret_cast<const float4*>(weight);

    int   rr[4] = {r4.x, r4.y, r4.z, r4.w};
    int   cc[4] = {c4.x, c4.y, c4.z, c4.w};
    float vv[4] = {v4.x, v4.y, v4.z, v4.w};

    // 4 independent gather->scale->reduce chains (ILP = 4).
    float4 w[4];
#pragma unroll
    for (int k = 0; k < 4; k++)
        w[k] = ldg_cg_v4(w4 + (size_t)cc[k] * DV + j);

#pragma unroll
    for (int k = 0; k < 4; k++) {
        float4 p;
        p.x = vv[k] * w[k].x;
        p.y = vv[k] * w[k].y;
        p.z = vv[k] * w[k].z;
        p.w = vv[k] * w[k].w;
        red_add_v4(out + (size_t)rr[k] * D + j * 4, p);
    }
}

extern "C" void kernel_launch(void* const* d_in, const int* in_sizes, int n_in,
                              void* d_out, int out_size)
{
    const int*   edge_row = (const int*)d_in[0];
    const int*   edge_col = (const int*)d_in[1];
    const float* edge_val = (const float*)d_in[2];
    const float* weight   = (const float*)d_in[3];
    const float* bias     = (const float*)d_in[4];
    float*       out      = (float*)d_out;

    int E = in_sizes[0];
    int n_vec = out_size / 4;  // number of float4 elements in out

    {
        int threads = 256;
        int blocks = (n_vec + threads - 1) / threads;
        init_out_kernel<<<blocks, threads>>>((float4*)out, bias, n_vec);
    }
    {
        int n_groups = E >> 2;  // E divisible by 4 (1.6M)
        int threads = 256;
        long long total = (long long)n_groups * 8;
        int blocks = (int)((total + threads - 1) / threads);
        spmm_edge_coop4_kernel<<<blocks, threads>>>(
            (const int4*)edge_row, (const int4*)edge_col,
            (const float4*)edge_val, weight, out, n_groups);
    }
}